// round 7
// baseline (speedup 1.0000x reference)
#include <cuda_runtime.h>
#include <math.h>
#include <stdint.h>

#define BB 4
#define NN 512
#define DD 4
#define HH 256
#define JT 64      // j-tile per CTA
#define IT 64      // i-values per CTA
#define KC 32      // K chunk of W_e2 staged in smem
#define PITCH 260  // smem row pitch (floats) for n2e/A tiles

// ---------------- scratch (no allocations allowed) ----------------
__device__ float g_A[BB * NN * HH];    // x[b,j] @ W_e1[0:4]
__device__ float g_C[BB * NN * HH];    // x[b,i] @ W_e1[4:8] + b_e1
__device__ float g_agg[BB * NN * HH];  // adjacency-weighted sum over i

// ---------------- kernel 1: precompute A, C, zero agg ----------------
__global__ void k_pre(const float* __restrict__ x,
                      const float* __restrict__ We1,
                      const float* __restrict__ be1) {
    int blk = blockIdx.x;       // global node index b*NN + j
    int h = threadIdx.x;        // 0..255
    const float* xr = x + blk * DD;
    float x0 = xr[0], x1 = xr[1], x2 = xr[2], x3 = xr[3];
    float a = x0 * We1[0 * HH + h] + x1 * We1[1 * HH + h] +
              x2 * We1[2 * HH + h] + x3 * We1[3 * HH + h];
    float c = x0 * We1[4 * HH + h] + x1 * We1[5 * HH + h] +
              x2 * We1[6 * HH + h] + x3 * We1[7 * HH + h] + be1[h];
    g_A[blk * HH + h] = a;
    g_C[blk * HH + h] = c;
    g_agg[blk * HH + h] = 0.f;
}

// ---------------- kernel 2: fused n2e -> e2e -> adj-weighted agg ----------------
__device__ __forceinline__ void cp16(uint32_t saddr, const void* gptr) {
    asm volatile("cp.async.cg.shared.global [%0], [%1], 16;\n" ::"r"(saddr), "l"(gptr));
}

// packed 2xFP32 FMA: acc.{lo,hi} += a.{lo,hi} * b.{lo,hi}  (rn rounding, bit-identical
// to two scalar fmaf) — only reachable via PTX fma.rn.f32x2 on sm_103a.
__device__ __forceinline__ void fma2(unsigned long long& acc, unsigned long long a,
                                     unsigned long long b) {
    asm("fma.rn.f32x2 %0, %1, %2, %0;" : "+l"(acc) : "l"(a), "l"(b));
}
__device__ __forceinline__ unsigned long long splat2(float v) {
    unsigned long long r;
    asm("mov.b64 %0, {%1, %1};" : "=l"(r) : "r"(__float_as_uint(v)));
    return r;
}

union F4U {
    float4 v;
    unsigned long long u[2];
};

extern __shared__ float smem[];

__global__ __launch_bounds__(256, 1) void k_main(const float* __restrict__ adj,
                                                 const float* __restrict__ We2,
                                                 const float* __restrict__ be2) {
    float* sA = smem;                   // [JT][PITCH]  A rows for this j-tile
    float* sN = smem + JT * PITCH;      // [JT][PITCH]  n2e tile (rebuilt per i)
    float* w0 = smem + 2 * JT * PITCH;  // [KC][HH]
    float* w1 = w0 + KC * HH;           // [KC][HH]

    int tid = threadIdx.x;
    int tm = tid & 7;        // row group 0..7
    int tn = tid >> 3;       // col group 0..31
    int j0 = blockIdx.x * JT;
    int i0 = blockIdx.y * IT;
    int b  = blockIdx.z;

    // per-thread epilogue bias fragment (cols tn*8 .. tn*8+7)
    float bias[8];
#pragma unroll
    for (int q = 0; q < 8; q++) bias[q] = be2[tn * 8 + q];

    // stage A rows for this j-tile once
    const float* gArow = g_A + (b * NN + j0) * HH;
    for (int idx = tid; idx < JT * (HH / 4); idx += 256) {
        int m  = idx / (HH / 4);
        int k4 = idx % (HH / 4);
        float4 v = ((const float4*)(gArow + m * HH))[k4];
        *((float4*)(sA + m * PITCH + k4 * 4)) = v;
    }

    float aggacc[8][8];
#pragma unroll
    for (int r = 0; r < 8; r++)
#pragma unroll
        for (int q = 0; q < 8; q++) aggacc[r][q] = 0.f;

    uint32_t w0a = (uint32_t)__cvta_generic_to_shared(w0);
    uint32_t w1a = (uint32_t)__cvta_generic_to_shared(w1);

    for (int ii = 0; ii < IT; ++ii) {
        int i = i0 + ii;
        __syncthreads();  // guards sN + w0/w1 reuse from previous iteration

        // async-prefetch W chunk 0 into w0
        {
            const float* src = We2;  // rows [0,KC)
#pragma unroll
            for (int q = 0; q < 8; q++) {
                int f = q * 256 + tid;  // float4 index 0..2047
                cp16(w0a + f * 16, src + f * 4);
            }
            asm volatile("cp.async.commit_group;\n");
        }

        // build n2e tile: relu(A[j,:] + C[i,:])   (thread owns column k = tid)
        float cv = g_C[(b * NN + i) * HH + tid];
#pragma unroll 8
        for (int m = 0; m < JT; m++)
            sN[m * PITCH + tid] = fmaxf(sA[m * PITCH + tid] + cv, 0.f);

        // packed accumulators: acc2[r][q] = cols {2q, 2q+1} of this thread's 8-col frag
        unsigned long long acc2[8][4];
#pragma unroll
        for (int r = 0; r < 8; r++)
#pragma unroll
            for (int q = 0; q < 4; q++) acc2[r][q] = 0ull;

        asm volatile("cp.async.wait_group 0;\n");
        __syncthreads();

#pragma unroll 1
        for (int c = 0; c < 8; c++) {  // 8 chunks of KC=32 -> K=256
            const float* wb = (c & 1) ? w1 : w0;
            if (c < 7) {
                uint32_t dsta = ((c + 1) & 1) ? w1a : w0a;
                const float* src = We2 + (c + 1) * KC * HH;
#pragma unroll
                for (int q = 0; q < 8; q++) {
                    int f = q * 256 + tid;
                    cp16(dsta + f * 16, src + f * 4);
                }
                asm volatile("cp.async.commit_group;\n");
            }

#pragma unroll 2
            for (int k4 = 0; k4 < KC; k4 += 4) {
                F4U b0[4], b1[4];  // b0 = cols 0-3 (pairs u[0],u[1]); b1 = cols 4-7
#pragma unroll
                for (int kk = 0; kk < 4; kk++) {
                    const float* wr = wb + (k4 + kk) * HH + tn * 8;
                    b0[kk].v = *((const float4*)wr);
                    b1[kk].v = *((const float4*)(wr + 4));
                }
#pragma unroll
                for (int r = 0; r < 8; r++) {
                    float4 af = *((const float4*)(sN + (r * 8 + tm) * PITCH + c * KC + k4));
                    float av[4] = {af.x, af.y, af.z, af.w};
#pragma unroll
                    for (int kk = 0; kk < 4; kk++) {
                        unsigned long long a2 = splat2(av[kk]);
                        fma2(acc2[r][0], a2, b0[kk].u[0]);
                        fma2(acc2[r][1], a2, b0[kk].u[1]);
                        fma2(acc2[r][2], a2, b1[kk].u[0]);
                        fma2(acc2[r][3], a2, b1[kk].u[1]);
                    }
                }
            }

            if (c < 7) {
                asm volatile("cp.async.wait_group 0;\n");
                __syncthreads();
            }
        }

        // epilogue: e2e = relu(acc + b_e2); agg += adj[b,i,j] * e2e
        const float* adjrow = adj + ((size_t)b * NN + i) * NN + j0;
#pragma unroll
        for (int r = 0; r < 8; r++) {
            float av = adjrow[r * 8 + tm];
#pragma unroll
            for (int q = 0; q < 4; q++) {
                unsigned long long p = acc2[r][q];
                float lo = __uint_as_float((unsigned)p);
                float hi = __uint_as_float((unsigned)(p >> 32));
                float e0 = fmaxf(lo + bias[2 * q], 0.f);
                float e1 = fmaxf(hi + bias[2 * q + 1], 0.f);
                aggacc[r][2 * q] += av * e0;
                aggacc[r][2 * q + 1] += av * e1;
            }
        }
    }

    // flush partial agg (8 i-blocks contribute per element)
    float* gout = g_agg + (b * NN + j0) * HH;
#pragma unroll
    for (int r = 0; r < 8; r++) {
        int m = r * 8 + tm;
#pragma unroll
        for (int q = 0; q < 8; q++)
            atomicAdd(gout + m * HH + tn * 8 + q, aggacc[r][q]);
    }
}

// ---------------- kernel 3: node MLP head + log_softmax ----------------
__global__ __launch_bounds__(256) void k_post(const float* __restrict__ x,
                                              const float* __restrict__ Wn1,
                                              const float* __restrict__ bn1,
                                              const float* __restrict__ Wn2,
                                              const float* __restrict__ bn2,
                                              const float* __restrict__ Wo1,
                                              const float* __restrict__ bo1,
                                              const float* __restrict__ Wo,
                                              const float* __restrict__ bo,
                                              float* __restrict__ out) {
    __shared__ float sIn[8 * HH];
    __shared__ float sTmp[8 * HH];
    __shared__ float sO4[8 * HH];
    __shared__ float s5[8 * 4];

    int tid = threadIdx.x;
    int g0 = blockIdx.x * 8;  // 8 nodes per CTA, never crosses a batch boundary

    for (int q = 0; q < 8; q++) sIn[q * 256 + tid] = g_agg[g0 * HH + q * 256 + tid];
    __syncthreads();

    float acc[8];

    // layer 1: relu(agg @ Wn1 + bn1) -> sTmp
#pragma unroll
    for (int nd = 0; nd < 8; nd++) acc[nd] = bn1[tid];
    for (int k = 0; k < HH; k += 4) {
        float w0_ = Wn1[(k + 0) * HH + tid], w1_ = Wn1[(k + 1) * HH + tid];
        float w2_ = Wn1[(k + 2) * HH + tid], w3_ = Wn1[(k + 3) * HH + tid];
#pragma unroll
        for (int nd = 0; nd < 8; nd++)
            acc[nd] += sIn[nd * HH + k] * w0_ + sIn[nd * HH + k + 1] * w1_ +
                       sIn[nd * HH + k + 2] * w2_ + sIn[nd * HH + k + 3] * w3_;
    }
#pragma unroll
    for (int nd = 0; nd < 8; nd++) sTmp[nd * HH + tid] = fmaxf(acc[nd], 0.f);
    __syncthreads();

    // layer 2: relu(out1 @ Wn2 + bn2) -> sIn
#pragma unroll
    for (int nd = 0; nd < 8; nd++) acc[nd] = bn2[tid];
    for (int k = 0; k < HH; k += 4) {
        float w0_ = Wn2[(k + 0) * HH + tid], w1_ = Wn2[(k + 1) * HH + tid];
        float w2_ = Wn2[(k + 2) * HH + tid], w3_ = Wn2[(k + 3) * HH + tid];
#pragma unroll
        for (int nd = 0; nd < 8; nd++)
            acc[nd] += sTmp[nd * HH + k] * w0_ + sTmp[nd * HH + k + 1] * w1_ +
                       sTmp[nd * HH + k + 2] * w2_ + sTmp[nd * HH + k + 3] * w3_;
    }
#pragma unroll
    for (int nd = 0; nd < 8; nd++) sIn[nd * HH + tid] = fmaxf(acc[nd], 0.f);
    __syncthreads();

    // layer 3: out4 = concat(x, out2) @ Wo1 + bo1   (no relu)
#pragma unroll
    for (int nd = 0; nd < 8; nd++) {
        acc[nd] = bo1[tid];
        const float* xr = x + (g0 + nd) * DD;
#pragma unroll
        for (int d = 0; d < DD; d++) acc[nd] += xr[d] * Wo1[d * HH + tid];
    }
    for (int k = 0; k < HH; k += 4) {
        float w0_ = Wo1[(4 + k + 0) * HH + tid], w1_ = Wo1[(4 + k + 1) * HH + tid];
        float w2_ = Wo1[(4 + k + 2) * HH + tid], w3_ = Wo1[(4 + k + 3) * HH + tid];
#pragma unroll
        for (int nd = 0; nd < 8; nd++)
            acc[nd] += sIn[nd * HH + k] * w0_ + sIn[nd * HH + k + 1] * w1_ +
                       sIn[nd * HH + k + 2] * w2_ + sIn[nd * HH + k + 3] * w3_;
    }
#pragma unroll
    for (int nd = 0; nd < 8; nd++) sO4[nd * HH + tid] = acc[nd];
    __syncthreads();

    // out5 = out4 @ Wo + bo  (256 -> 4), then log_softmax
    if (tid < 32) {
        int nd = tid >> 2, c = tid & 3;
        float a = bo[c];
        for (int k = 0; k < HH; k += 4) {
            a += sO4[nd * HH + k + 0] * Wo[(k + 0) * 4 + c];
            a += sO4[nd * HH + k + 1] * Wo[(k + 1) * 4 + c];
            a += sO4[nd * HH + k + 2] * Wo[(k + 2) * 4 + c];
            a += sO4[nd * HH + k + 3] * Wo[(k + 3) * 4 + c];
        }
        s5[nd * 4 + c] = a;
    }
    __syncthreads();
    if (tid < 8) {
        float v0 = s5[tid * 4 + 0], v1 = s5[tid * 4 + 1];
        float v2 = s5[tid * 4 + 2], v3 = s5[tid * 4 + 3];
        float m = fmaxf(fmaxf(v0, v1), fmaxf(v2, v3));
        // full logsumexp (FIX: previously subtracted m twice)
        float lse = m + logf(expf(v0 - m) + expf(v1 - m) + expf(v2 - m) + expf(v3 - m));
        float* o = out + (size_t)(g0 + tid) * 4;
        o[0] = v0 - lse;
        o[1] = v1 - lse;
        o[2] = v2 - lse;
        o[3] = v3 - lse;
    }
}

// ---------------- launch ----------------
extern "C" void kernel_launch(void* const* d_in, const int* in_sizes, int n_in,
                              void* d_out, int out_size) {
    const float* x   = (const float*)d_in[0];
    const float* adj = (const float*)d_in[1];
    const float* We1 = (const float*)d_in[2];
    const float* be1 = (const float*)d_in[3];
    const float* We2 = (const float*)d_in[4];
    const float* be2 = (const float*)d_in[5];
    const float* Wn1 = (const float*)d_in[6];
    const float* bn1 = (const float*)d_in[7];
    const float* Wn2 = (const float*)d_in[8];
    const float* bn2 = (const float*)d_in[9];
    const float* Wo1 = (const float*)d_in[10];
    const float* bo1 = (const float*)d_in[11];
    const float* Wo  = (const float*)d_in[12];
    const float* bo  = (const float*)d_in[13];
    float* out = (float*)d_out;

    size_t smem_bytes = (size_t)(2 * JT * PITCH + 2 * KC * HH) * sizeof(float);
    cudaFuncSetAttribute(k_main, cudaFuncAttributeMaxDynamicSharedMemorySize,
                         (int)smem_bytes);

    k_pre<<<BB * NN, HH>>>(x, We1, be1);
    dim3 g2(NN / JT, NN / IT, BB);
    k_main<<<g2, 256, smem_bytes>>>(adj, We2, be2);
    k_post<<<BB * NN / 8, 256>>>(x, Wn1, bn1, Wn2, bn2, Wo1, bo1, Wo, bo, out);
}

// round 12
// speedup vs baseline: 2.0561x; 2.0561x over previous
#include <cuda_runtime.h>
#include <cuda_bf16.h>
#include <math.h>
#include <stdint.h>

#define BB 4
#define NN 512
#define DD 4
#define HH 256
#define NNODE (BB * NN)  // 2048

#define JT 64   // j rows per CTA
#define CT 128  // output cols per CTA
#define IT 64   // i per CTA

#define SNK 264           // bf16 elems per smem row (128B-conflict-free: 528B stride -> banks 4r)
#define SROW (SNK * 2)    // 528 bytes

// smem offsets (bytes)
#define SM_NHI 0
#define SM_NLO (JT * SROW)              // 33792
#define SM_WHI (2 * JT * SROW)          // 67584
#define SM_WLO (SM_WHI + CT * SROW)     // 135168
#define SM_ADJ (SM_WLO + CT * SROW)     // 202752
#define SM_TOTAL (SM_ADJ + JT * 4)      // 203008

// ---------------- scratch ----------------
__device__ float g_A[NNODE * HH];           // x[j] @ We1[0:4]        row-major [node][k]
__device__ float g_C[NNODE * HH];           // x[i] @ We1[4:8] + b_e1 row-major [node][k]
__device__ float g_agg[NNODE * HH];
__device__ __nv_bfloat16 g_Wt_hi[HH * HH];  // [n][k] = bf16(We2[k][n])
__device__ __nv_bfloat16 g_Wt_lo[HH * HH];  // residual

__device__ __forceinline__ uint32_t smem_to_u32(const void* p) {
    uint32_t a;
    asm("{ .reg .u64 t; cvta.to.shared.u64 t, %1; cvt.u32.u64 %0, t; }" : "=r"(a) : "l"(p));
    return a;
}

#define LDSM_X4(R, addr)                                                      \
    asm volatile("ldmatrix.sync.aligned.m8n8.x4.shared.b16 {%0,%1,%2,%3}, [%4];" \
                 : "=r"((R)[0]), "=r"((R)[1]), "=r"((R)[2]), "=r"((R)[3])      \
                 : "r"(addr))
#define LDSM_X2(R, addr)                                                \
    asm volatile("ldmatrix.sync.aligned.m8n8.x2.shared.b16 {%0,%1}, [%2];" \
                 : "=r"((R)[0]), "=r"((R)[1])                            \
                 : "r"(addr))
#define MMA16816(D, A, Bf)                                                          \
    asm volatile(                                                                   \
        "mma.sync.aligned.m16n8k16.row.col.f32.bf16.bf16.f32 "                      \
        "{%0,%1,%2,%3}, {%4,%5,%6,%7}, {%8,%9}, {%0,%1,%2,%3};"                     \
        : "+f"((D)[0]), "+f"((D)[1]), "+f"((D)[2]), "+f"((D)[3])                    \
        : "r"((A)[0]), "r"((A)[1]), "r"((A)[2]), "r"((A)[3]), "r"((Bf)[0]),         \
          "r"((Bf)[1]))

// ---------------- kernel 1: precompute A, C, zero agg ----------------
__global__ void k_pre(const float* __restrict__ x,
                      const float* __restrict__ We1,
                      const float* __restrict__ be1) {
    int blk = blockIdx.x;
    int h = threadIdx.x;
    const float* xr = x + blk * DD;
    float x0 = xr[0], x1 = xr[1], x2 = xr[2], x3 = xr[3];
    float a = x0 * We1[0 * HH + h] + x1 * We1[1 * HH + h] +
              x2 * We1[2 * HH + h] + x3 * We1[3 * HH + h];
    float c = x0 * We1[4 * HH + h] + x1 * We1[5 * HH + h] +
              x2 * We1[6 * HH + h] + x3 * We1[7 * HH + h] + be1[h];
    g_A[blk * HH + h] = a;
    g_C[blk * HH + h] = c;
    g_agg[blk * HH + h] = 0.f;
}

// ---------------- kernel 1b: transpose + hi/lo split W_e2 ----------------
__global__ void k_prew(const float* __restrict__ We2) {
    int n = blockIdx.x;
    int k = threadIdx.x;
    float v = We2[k * HH + n];
    __nv_bfloat16 h = __float2bfloat16(v);
    float r = v - __bfloat162float(h);
    g_Wt_hi[n * HH + k] = h;
    g_Wt_lo[n * HH + k] = __float2bfloat16(r);
}

// ---------------- kernel 2: fused n2e -> HMMA e2e -> adj-weighted agg ----------------
extern __shared__ char smem_raw[];

__global__ __launch_bounds__(256, 1) void k_main(const float* __restrict__ adj,
                                                 const float* __restrict__ be2) {
    uint32_t sm = smem_to_u32(smem_raw);
    int tid = threadIdx.x;
    int lane = tid & 31;
    int wid = tid >> 5;
    int mblk = (wid & 1) * 32;   // warp's 32 m-rows within 64
    int nblk = (wid >> 1) * 32;  // warp's 32 n-cols within 128

    int jb = blockIdx.x >> 1, cb = blockIdx.x & 1;
    int j0 = jb * JT, c0 = cb * CT, i0 = blockIdx.y * IT, b = blockIdx.z;
    int nodebase = b * NN + j0;

    float* sAdj = (float*)(smem_raw + SM_ADJ);

    // ---- stage W hi/lo [n][k] once (coalesced 16B chunks) ----
    for (int idx = tid; idx < CT * 32; idx += 256) {
        int row = idx >> 5;
        int ch = idx & 31;
        const uint4 vh = *(const uint4*)(g_Wt_hi + (size_t)(c0 + row) * HH + ch * 8);
        const uint4 vl = *(const uint4*)(g_Wt_lo + (size_t)(c0 + row) * HH + ch * 8);
        *(uint4*)(smem_raw + SM_WHI + row * SROW + ch * 16) = vh;
        *(uint4*)(smem_raw + SM_WLO + row * SROW + ch * 16) = vl;
    }

    // ---- per-thread bias fragment (8 cols) ----
    float biasr[4][2];
#pragma unroll
    for (int nt = 0; nt < 4; nt++) {
        int cbase = c0 + nblk + nt * 8 + (lane & 3) * 2;
        biasr[nt][0] = be2[cbase];
        biasr[nt][1] = be2[cbase + 1];
    }

    // ---- ldmatrix address offsets (within tile bases) ----
    uint32_t aoff[2], boff[4];
    {
        int arow = mblk + (lane & 15);
        int akoff = (lane >> 4) * 8;
#pragma unroll
        for (int mi = 0; mi < 2; mi++)
            aoff[mi] = (uint32_t)(((arow + mi * 16) * SNK + akoff) * 2);
        int brow = nblk + (lane & 7);
        int bkoff = ((lane >> 3) & 1) * 8;
#pragma unroll
        for (int nt = 0; nt < 4; nt++)
            boff[nt] = (uint32_t)(((brow + nt * 8) * SNK + bkoff) * 2);
    }
    uint32_t sNhi = sm + SM_NHI, sNlo = sm + SM_NLO;
    uint32_t sWhi = sm + SM_WHI, sWlo = sm + SM_WLO;

    float aggacc[2][4][4];
#pragma unroll
    for (int mi = 0; mi < 2; mi++)
#pragma unroll
        for (int nt = 0; nt < 4; nt++)
#pragma unroll
            for (int e = 0; e < 4; e++) aggacc[mi][nt][e] = 0.f;

    __syncthreads();  // W staged

    for (int ii = 0; ii < IT; ++ii) {
        int i = i0 + ii;
        const float* Crow = g_C + (size_t)(b * NN + i) * HH;

        // ---- build n2e hi/lo tiles (coalesced: consecutive threads -> consecutive k) ----
#pragma unroll 4
        for (int idx = tid; idx < JT * 128; idx += 256) {
            int row = idx >> 7;
            int k = (idx & 127) * 2;
            float2 a2 = *(const float2*)(g_A + (size_t)(nodebase + row) * HH + k);
            float2 c2 = *(const float2*)(Crow + k);
            float v0 = fmaxf(a2.x + c2.x, 0.f);
            float v1 = fmaxf(a2.y + c2.y, 0.f);
            __nv_bfloat162 h2 = __floats2bfloat162_rn(v0, v1);
            float r0 = v0 - __bfloat162float(h2.x);
            float r1 = v1 - __bfloat162float(h2.y);
            __nv_bfloat162 l2 = __floats2bfloat162_rn(r0, r1);
            *(uint32_t*)(smem_raw + SM_NHI + row * SROW + k * 2) = *(uint32_t*)&h2;
            *(uint32_t*)(smem_raw + SM_NLO + row * SROW + k * 2) = *(uint32_t*)&l2;
        }
        if (tid < JT) sAdj[tid] = adj[((size_t)b * NN + i) * NN + j0 + tid];
        __syncthreads();

        // ---- 3 compensated HMMA passes ----
        float acc[2][4][4];
#pragma unroll
        for (int mi = 0; mi < 2; mi++)
#pragma unroll
            for (int nt = 0; nt < 4; nt++)
#pragma unroll
                for (int e = 0; e < 4; e++) acc[mi][nt][e] = 0.f;

#pragma unroll 1
        for (int p = 0; p < 3; p++) {
            uint32_t Ab = (p < 2) ? sNhi : sNlo;
            uint32_t Bb = (p == 1) ? sWlo : sWhi;
#pragma unroll
            for (int ks = 0; ks < 16; ks++) {
                uint32_t af[2][4], bf[4][2];
#pragma unroll
                for (int mi = 0; mi < 2; mi++) LDSM_X4(af[mi], Ab + aoff[mi] + ks * 32);
#pragma unroll
                for (int nt = 0; nt < 4; nt++) LDSM_X2(bf[nt], Bb + boff[nt] + ks * 32);
#pragma unroll
                for (int mi = 0; mi < 2; mi++)
#pragma unroll
                    for (int nt = 0; nt < 4; nt++) MMA16816(acc[mi][nt], af[mi], bf[nt]);
            }
        }

        // ---- epilogue: relu(acc + bias) * adj -> aggacc (registers only) ----
        float adjv[4];
#pragma unroll
        for (int q = 0; q < 4; q++) {
            int mi = q >> 1, dh = q & 1;
            adjv[q] = sAdj[mblk + mi * 16 + dh * 8 + (lane >> 2)];
        }
#pragma unroll
        for (int mi = 0; mi < 2; mi++)
#pragma unroll
            for (int nt = 0; nt < 4; nt++)
#pragma unroll
                for (int e = 0; e < 4; e++) {
                    int dh = e >> 1;  // row half (+8)
                    float ev = fmaxf(acc[mi][nt][e] + biasr[nt][e & 1], 0.f);
                    aggacc[mi][nt][e] += adjv[mi * 2 + dh] * ev;
                }
        __syncthreads();  // epilogue sAdj reads done before next build overwrites
    }

    // ---- flush agg (atomic; 8 ib-splits contribute per element) ----
#pragma unroll
    for (int mi = 0; mi < 2; mi++)
#pragma unroll
        for (int nt = 0; nt < 4; nt++)
#pragma unroll
            for (int e = 0; e < 4; e++) {
                int row = j0 + mblk + mi * 16 + (e >> 1) * 8 + (lane >> 2);
                int col = c0 + nblk + nt * 8 + (lane & 3) * 2 + (e & 1);
                atomicAdd(g_agg + (size_t)(b * NN + row) * HH + col, aggacc[mi][nt][e]);
            }
}

// ---------------- kernel 3: node MLP head + log_softmax ----------------
__global__ __launch_bounds__(256) void k_post(const float* __restrict__ x,
                                              const float* __restrict__ Wn1,
                                              const float* __restrict__ bn1,
                                              const float* __restrict__ Wn2,
                                              const float* __restrict__ bn2,
                                              const float* __restrict__ Wo1,
                                              const float* __restrict__ bo1,
                                              const float* __restrict__ Wo,
                                              const float* __restrict__ bo,
                                              float* __restrict__ out) {
    __shared__ float sIn[8 * HH];
    __shared__ float sTmp[8 * HH];
    __shared__ float sO4[8 * HH];
    __shared__ float s5[8 * 4];

    int tid = threadIdx.x;
    int g0 = blockIdx.x * 8;

    for (int q = 0; q < 8; q++) sIn[q * 256 + tid] = g_agg[g0 * HH + q * 256 + tid];
    __syncthreads();

    float acc[8];
#pragma unroll
    for (int nd = 0; nd < 8; nd++) acc[nd] = bn1[tid];
    for (int k = 0; k < HH; k += 4) {
        float w0_ = Wn1[(k + 0) * HH + tid], w1_ = Wn1[(k + 1) * HH + tid];
        float w2_ = Wn1[(k + 2) * HH + tid], w3_ = Wn1[(k + 3) * HH + tid];
#pragma unroll
        for (int nd = 0; nd < 8; nd++)
            acc[nd] += sIn[nd * HH + k] * w0_ + sIn[nd * HH + k + 1] * w1_ +
                       sIn[nd * HH + k + 2] * w2_ + sIn[nd * HH + k + 3] * w3_;
    }
#pragma unroll
    for (int nd = 0; nd < 8; nd++) sTmp[nd * HH + tid] = fmaxf(acc[nd], 0.f);
    __syncthreads();

#pragma unroll
    for (int nd = 0; nd < 8; nd++) acc[nd] = bn2[tid];
    for (int k = 0; k < HH; k += 4) {
        float w0_ = Wn2[(k + 0) * HH + tid], w1_ = Wn2[(k + 1) * HH + tid];
        float w2_ = Wn2[(k + 2) * HH + tid], w3_ = Wn2[(k + 3) * HH + tid];
#pragma unroll
        for (int nd = 0; nd < 8; nd++)
            acc[nd] += sTmp[nd * HH + k] * w0_ + sTmp[nd * HH + k + 1] * w1_ +
                       sTmp[nd * HH + k + 2] * w2_ + sTmp[nd * HH + k + 3] * w3_;
    }
#pragma unroll
    for (int nd = 0; nd < 8; nd++) sIn[nd * HH + tid] = fmaxf(acc[nd], 0.f);
    __syncthreads();

#pragma unroll
    for (int nd = 0; nd < 8; nd++) {
        acc[nd] = bo1[tid];
        const float* xr = x + (g0 + nd) * DD;
#pragma unroll
        for (int d = 0; d < DD; d++) acc[nd] += xr[d] * Wo1[d * HH + tid];
    }
    for (int k = 0; k < HH; k += 4) {
        float w0_ = Wo1[(4 + k + 0) * HH + tid], w1_ = Wo1[(4 + k + 1) * HH + tid];
        float w2_ = Wo1[(4 + k + 2) * HH + tid], w3_ = Wo1[(4 + k + 3) * HH + tid];
#pragma unroll
        for (int nd = 0; nd < 8; nd++)
            acc[nd] += sIn[nd * HH + k] * w0_ + sIn[nd * HH + k + 1] * w1_ +
                       sIn[nd * HH + k + 2] * w2_ + sIn[nd * HH + k + 3] * w3_;
    }
#pragma unroll
    for (int nd = 0; nd < 8; nd++) sO4[nd * HH + tid] = acc[nd];
    __syncthreads();

    if (tid < 32) {
        int nd = tid >> 2, c = tid & 3;
        float a = bo[c];
        for (int k = 0; k < HH; k += 4) {
            a += sO4[nd * HH + k + 0] * Wo[(k + 0) * 4 + c];
            a += sO4[nd * HH + k + 1] * Wo[(k + 1) * 4 + c];
            a += sO4[nd * HH + k + 2] * Wo[(k + 2) * 4 + c];
            a += sO4[nd * HH + k + 3] * Wo[(k + 3) * 4 + c];
        }
        s5[nd * 4 + c] = a;
    }
    __syncthreads();
    if (tid < 8) {
        float v0 = s5[tid * 4 + 0], v1 = s5[tid * 4 + 1];
        float v2 = s5[tid * 4 + 2], v3 = s5[tid * 4 + 3];
        float m = fmaxf(fmaxf(v0, v1), fmaxf(v2, v3));
        float lse = m + logf(expf(v0 - m) + expf(v1 - m) + expf(v2 - m) + expf(v3 - m));
        float* o = out + (size_t)(g0 + tid) * 4;
        o[0] = v0 - lse;
        o[1] = v1 - lse;
        o[2] = v2 - lse;
        o[3] = v3 - lse;
    }
}

// ---------------- launch ----------------
extern "C" void kernel_launch(void* const* d_in, const int* in_sizes, int n_in,
                              void* d_out, int out_size) {
    const float* x   = (const float*)d_in[0];
    const float* adj = (const float*)d_in[1];
    const float* We1 = (const float*)d_in[2];
    const float* be1 = (const float*)d_in[3];
    const float* We2 = (const float*)d_in[4];
    const float* be2 = (const float*)d_in[5];
    const float* Wn1 = (const float*)d_in[6];
    const float* bn1 = (const float*)d_in[7];
    const float* Wn2 = (const float*)d_in[8];
    const float* bn2 = (const float*)d_in[9];
    const float* Wo1 = (const float*)d_in[10];
    const float* bo1 = (const float*)d_in[11];
    const float* Wo  = (const float*)d_in[12];
    const float* bo  = (const float*)d_in[13];
    float* out = (float*)d_out;

    cudaFuncSetAttribute(k_main, cudaFuncAttributeMaxDynamicSharedMemorySize, SM_TOTAL);

    k_pre<<<NNODE, HH>>>(x, We1, be1);
    k_prew<<<HH, HH>>>(We2);
    dim3 g2(16, 8, 4);  // x = jb*2 + cb, y = ib, z = b
    k_main<<<g2, 256, SM_TOTAL>>>(adj, be2);
    k_post<<<NNODE / 8, 256>>>(x, Wn1, bn1, Wn2, bn2, Wo1, bo1, Wo, bo, out);
}

// round 14
// speedup vs baseline: 2.6038x; 1.2664x over previous
#include <cuda_runtime.h>
#include <cuda_bf16.h>
#include <math.h>
#include <stdint.h>

#define BB 4
#define NN 512
#define DD 4
#define HH 256
#define NNODE (BB * NN)  // 2048

#define JT 64   // j rows per CTA
#define CT 128  // output cols per CTA
#define IT 64   // i per CTA

#define SNK 264           // bf16 elems per smem row (528B stride, conflict-free)
#define SROW (SNK * 2)    // 528 bytes

// smem offsets (bytes)
#define SM_NHI 0
#define SM_NLO (JT * SROW)              // 33792
#define SM_WHI (2 * JT * SROW)          // 67584
#define SM_WLO (SM_WHI + CT * SROW)     // 135168
#define SM_ADJ (SM_WLO + CT * SROW)     // 202752
#define SM_TOTAL (SM_ADJ + JT * 4)      // 203008

// ---------------- scratch ----------------
__device__ float g_A[NNODE * HH];           // x[j] @ We1[0:4]        row-major [node][k]
__device__ float g_C[NNODE * HH];           // x[i] @ We1[4:8] + b_e1 row-major [node][k]
__device__ float g_agg[NNODE * HH];
__device__ __nv_bfloat16 g_Wt_hi[HH * HH];  // [n][k] = bf16(We2[k][n])
__device__ __nv_bfloat16 g_Wt_lo[HH * HH];  // residual

__device__ __forceinline__ uint32_t smem_to_u32(const void* p) {
    uint32_t a;
    asm("{ .reg .u64 t; cvta.to.shared.u64 t, %1; cvt.u32.u64 %0, t; }" : "=r"(a) : "l"(p));
    return a;
}

#define LDSM_X4(R, addr)                                                      \
    asm volatile("ldmatrix.sync.aligned.m8n8.x4.shared.b16 {%0,%1,%2,%3}, [%4];" \
                 : "=r"((R)[0]), "=r"((R)[1]), "=r"((R)[2]), "=r"((R)[3])      \
                 : "r"(addr))
#define MMA16816(D, A, Bf)                                                          \
    asm volatile(                                                                   \
        "mma.sync.aligned.m16n8k16.row.col.f32.bf16.bf16.f32 "                      \
        "{%0,%1,%2,%3}, {%4,%5,%6,%7}, {%8,%9}, {%0,%1,%2,%3};"                     \
        : "+f"((D)[0]), "+f"((D)[1]), "+f"((D)[2]), "+f"((D)[3])                    \
        : "r"((A)[0]), "r"((A)[1]), "r"((A)[2]), "r"((A)[3]), "r"((Bf)[0]),         \
          "r"((Bf)[1]))

// ---------------- kernel 1: precompute A, C, zero agg ----------------
__global__ void k_pre(const float* __restrict__ x,
                      const float* __restrict__ We1,
                      const float* __restrict__ be1) {
    int blk = blockIdx.x;
    int h = threadIdx.x;
    const float* xr = x + blk * DD;
    float x0 = xr[0], x1 = xr[1], x2 = xr[2], x3 = xr[3];
    float a = x0 * We1[0 * HH + h] + x1 * We1[1 * HH + h] +
              x2 * We1[2 * HH + h] + x3 * We1[3 * HH + h];
    float c = x0 * We1[4 * HH + h] + x1 * We1[5 * HH + h] +
              x2 * We1[6 * HH + h] + x3 * We1[7 * HH + h] + be1[h];
    g_A[blk * HH + h] = a;
    g_C[blk * HH + h] = c;
    g_agg[blk * HH + h] = 0.f;
}

// ---------------- kernel 1b: transpose + hi/lo split W_e2 ----------------
__global__ void k_prew(const float* __restrict__ We2) {
    int n = blockIdx.x;
    int k = threadIdx.x;
    float v = We2[k * HH + n];
    __nv_bfloat16 h = __float2bfloat16(v);
    float r = v - __bfloat162float(h);
    g_Wt_hi[n * HH + k] = h;
    g_Wt_lo[n * HH + k] = __float2bfloat16(r);
}

// ---------------- kernel 2: fused n2e -> HMMA e2e -> adj-weighted agg ----------------
extern __shared__ char smem_raw[];

__global__ __launch_bounds__(256, 1) void k_main(const float* __restrict__ adj,
                                                 const float* __restrict__ be2) {
    uint32_t sm = smem_to_u32(smem_raw);
    int tid = threadIdx.x;
    int lane = tid & 31;
    int wid = tid >> 5;
    int mblk = (wid & 1) * 32;   // warp's 32 m-rows within 64
    int nblk = (wid >> 1) * 32;  // warp's 32 n-cols within 128

    int jb = blockIdx.x >> 1, cb = blockIdx.x & 1;
    int j0 = jb * JT, c0 = cb * CT, i0 = blockIdx.y * IT, b = blockIdx.z;
    int nodebase = b * NN + j0;

    float* sAdj = (float*)(smem_raw + SM_ADJ);

    // ---- stage W hi/lo [n][k] once (coalesced 16B chunks) ----
    for (int idx = tid; idx < CT * 32; idx += 256) {
        int row = idx >> 5;
        int ch = idx & 31;
        const uint4 vh = *(const uint4*)(g_Wt_hi + (size_t)(c0 + row) * HH + ch * 8);
        const uint4 vl = *(const uint4*)(g_Wt_lo + (size_t)(c0 + row) * HH + ch * 8);
        *(uint4*)(smem_raw + SM_WHI + row * SROW + ch * 16) = vh;
        *(uint4*)(smem_raw + SM_WLO + row * SROW + ch * 16) = vl;
    }

    // ---- register-resident A tile: thread owns fixed k-pair, 32 rows ----
    int kpair = tid & 127;   // element pair index: elements 2*kpair, 2*kpair+1
    int rowhalf = tid >> 7;  // rows 2t + rowhalf
    float2 Areg[32];
#pragma unroll
    for (int t = 0; t < 32; t++) {
        int row = 2 * t + rowhalf;
        Areg[t] = *(const float2*)(g_A + (size_t)(nodebase + row) * HH + kpair * 2);
    }

    // ---- per-thread bias fragment (8 cols) ----
    float biasr[4][2];
#pragma unroll
    for (int nt = 0; nt < 4; nt++) {
        int cbase = c0 + nblk + nt * 8 + (lane & 3) * 2;
        biasr[nt][0] = be2[cbase];
        biasr[nt][1] = be2[cbase + 1];
    }

    // ---- ldmatrix address offsets ----
    uint32_t aoff[2], boff4[2];
    {
        int arow = mblk + (lane & 15);
        int akoff = (lane >> 4) * 8;
#pragma unroll
        for (int mi = 0; mi < 2; mi++)
            aoff[mi] = (uint32_t)(((arow + mi * 16) * SNK + akoff) * 2);
        // B x4: lane group g=lane>>3 -> matrix g: rows nblk+(g>>1)*8+(lane&7), k-byte (g&1)*16
        int g = lane >> 3;
        int brow = nblk + ((g >> 1) * 8) + (lane & 7);
        int bkb = (g & 1) * 16;
#pragma unroll
        for (int u = 0; u < 2; u++)
            boff4[u] = (uint32_t)((brow + u * 16) * SROW + bkb);
    }
    uint32_t sNhi = sm + SM_NHI, sNlo = sm + SM_NLO;
    uint32_t sWhi = sm + SM_WHI, sWlo = sm + SM_WLO;

    float aggacc[2][4][4];
#pragma unroll
    for (int mi = 0; mi < 2; mi++)
#pragma unroll
        for (int nt = 0; nt < 4; nt++)
#pragma unroll
            for (int e = 0; e < 4; e++) aggacc[mi][nt][e] = 0.f;

    __syncthreads();  // W staged

    for (int ii = 0; ii < IT; ++ii) {
        int i = i0 + ii;

        // ---- build n2e hi/lo tiles (A in regs; C: 8B/thread from L1) ----
        float2 c2 = *(const float2*)(g_C + (size_t)(b * NN + i) * HH + kpair * 2);
        {
            uint32_t base_hi = sNhi + rowhalf * SROW + kpair * 4;
            uint32_t base_lo = sNlo + rowhalf * SROW + kpair * 4;
#pragma unroll
            for (int t = 0; t < 32; t++) {
                float v0 = fmaxf(Areg[t].x + c2.x, 0.f);
                float v1 = fmaxf(Areg[t].y + c2.y, 0.f);
                __nv_bfloat162 h2 = __floats2bfloat162_rn(v0, v1);
                float r0 = v0 - __bfloat162float(h2.x);
                float r1 = v1 - __bfloat162float(h2.y);
                __nv_bfloat162 l2 = __floats2bfloat162_rn(r0, r1);
                uint32_t hb = *(uint32_t*)&h2;
                uint32_t lb = *(uint32_t*)&l2;
                asm volatile("st.shared.b32 [%0], %1;" ::"r"(base_hi + t * 2 * SROW), "r"(hb));
                asm volatile("st.shared.b32 [%0], %1;" ::"r"(base_lo + t * 2 * SROW), "r"(lb));
            }
        }
        if (tid < JT) sAdj[tid] = adj[((size_t)b * NN + i) * NN + j0 + tid];
        __syncthreads();

        // ---- 3 compensated HMMA passes ----
        float acc[2][4][4];
#pragma unroll
        for (int mi = 0; mi < 2; mi++)
#pragma unroll
            for (int nt = 0; nt < 4; nt++)
#pragma unroll
                for (int e = 0; e < 4; e++) acc[mi][nt][e] = 0.f;

#pragma unroll 1
        for (int p = 0; p < 3; p++) {
            uint32_t Ab = (p < 2) ? sNhi : sNlo;
            uint32_t Bb = (p == 1) ? sWlo : sWhi;
#pragma unroll
            for (int ks = 0; ks < 16; ks++) {
                uint32_t af[2][4], B4[2][4];
#pragma unroll
                for (int mi = 0; mi < 2; mi++) LDSM_X4(af[mi], Ab + aoff[mi] + ks * 32);
#pragma unroll
                for (int u = 0; u < 2; u++) LDSM_X4(B4[u], Bb + boff4[u] + ks * 32);
#pragma unroll
                for (int mi = 0; mi < 2; mi++)
#pragma unroll
                    for (int u = 0; u < 2; u++) {
                        MMA16816(acc[mi][2 * u], af[mi], &B4[u][0]);
                        MMA16816(acc[mi][2 * u + 1], af[mi], &B4[u][2]);
                    }
            }
        }

        // ---- epilogue: relu(acc + bias) * adj -> aggacc (registers only) ----
        float adjv[4];
#pragma unroll
        for (int q = 0; q < 4; q++) {
            int mi = q >> 1, dh = q & 1;
            adjv[q] = sAdj[mblk + mi * 16 + dh * 8 + (lane >> 2)];
        }
#pragma unroll
        for (int mi = 0; mi < 2; mi++)
#pragma unroll
            for (int nt = 0; nt < 4; nt++)
#pragma unroll
                for (int e = 0; e < 4; e++) {
                    int dh = e >> 1;
                    float ev = fmaxf(acc[mi][nt][e] + biasr[nt][e & 1], 0.f);
                    aggacc[mi][nt][e] += adjv[mi * 2 + dh] * ev;
                }
        __syncthreads();  // N smem reads done before next build overwrites
    }

    // ---- flush agg (atomic; 8 ib-splits contribute per element) ----
#pragma unroll
    for (int mi = 0; mi < 2; mi++)
#pragma unroll
        for (int nt = 0; nt < 4; nt++)
#pragma unroll
            for (int e = 0; e < 4; e++) {
                int row = j0 + mblk + mi * 16 + (e >> 1) * 8 + (lane >> 2);
                int col = c0 + nblk + nt * 8 + (lane & 3) * 2 + (e & 1);
                atomicAdd(g_agg + (size_t)(b * NN + row) * HH + col, aggacc[mi][nt][e]);
            }
}

// ---------------- kernel 3: node MLP head + log_softmax (16 nodes/CTA) ----------------
#define ND 16
__global__ __launch_bounds__(256) void k_post(const float* __restrict__ x,
                                              const float* __restrict__ Wn1,
                                              const float* __restrict__ bn1,
                                              const float* __restrict__ Wn2,
                                              const float* __restrict__ bn2,
                                              const float* __restrict__ Wo1,
                                              const float* __restrict__ bo1,
                                              const float* __restrict__ Wo,
                                              const float* __restrict__ bo,
                                              float* __restrict__ out) {
    __shared__ float sIn[ND * HH];
    __shared__ float sTmp[ND * HH];
    __shared__ float sO4[ND * HH];
    __shared__ float s5[ND * 4];

    int tid = threadIdx.x;
    int g0 = blockIdx.x * ND;

    for (int q = 0; q < ND; q++) sIn[q * 256 + tid] = g_agg[g0 * HH + q * 256 + tid];
    __syncthreads();

    float acc[ND];

    // layer 1: relu(agg @ Wn1 + bn1)
#pragma unroll
    for (int nd = 0; nd < ND; nd++) acc[nd] = bn1[tid];
    for (int k = 0; k < HH; k += 4) {
        float w0_ = Wn1[(k + 0) * HH + tid], w1_ = Wn1[(k + 1) * HH + tid];
        float w2_ = Wn1[(k + 2) * HH + tid], w3_ = Wn1[(k + 3) * HH + tid];
#pragma unroll
        for (int nd = 0; nd < ND; nd++)
            acc[nd] += sIn[nd * HH + k] * w0_ + sIn[nd * HH + k + 1] * w1_ +
                       sIn[nd * HH + k + 2] * w2_ + sIn[nd * HH + k + 3] * w3_;
    }
#pragma unroll
    for (int nd = 0; nd < ND; nd++) sTmp[nd * HH + tid] = fmaxf(acc[nd], 0.f);
    __syncthreads();

    // layer 2
#pragma unroll
    for (int nd = 0; nd < ND; nd++) acc[nd] = bn2[tid];
    for (int k = 0; k < HH; k += 4) {
        float w0_ = Wn2[(k + 0) * HH + tid], w1_ = Wn2[(k + 1) * HH + tid];
        float w2_ = Wn2[(k + 2) * HH + tid], w3_ = Wn2[(k + 3) * HH + tid];
#pragma unroll
        for (int nd = 0; nd < ND; nd++)
            acc[nd] += sTmp[nd * HH + k] * w0_ + sTmp[nd * HH + k + 1] * w1_ +
                       sTmp[nd * HH + k + 2] * w2_ + sTmp[nd * HH + k + 3] * w3_;
    }
#pragma unroll
    for (int nd = 0; nd < ND; nd++) sIn[nd * HH + tid] = fmaxf(acc[nd], 0.f);
    __syncthreads();

    // layer 3: out4 = concat(x, out2) @ Wo1 + bo1 (no relu)
#pragma unroll
    for (int nd = 0; nd < ND; nd++) {
        acc[nd] = bo1[tid];
        const float* xr = x + (g0 + nd) * DD;
#pragma unroll
        for (int d = 0; d < DD; d++) acc[nd] += xr[d] * Wo1[d * HH + tid];
    }
    for (int k = 0; k < HH; k += 4) {
        float w0_ = Wo1[(4 + k + 0) * HH + tid], w1_ = Wo1[(4 + k + 1) * HH + tid];
        float w2_ = Wo1[(4 + k + 2) * HH + tid], w3_ = Wo1[(4 + k + 3) * HH + tid];
#pragma unroll
        for (int nd = 0; nd < ND; nd++)
            acc[nd] += sIn[nd * HH + k] * w0_ + sIn[nd * HH + k + 1] * w1_ +
                       sIn[nd * HH + k + 2] * w2_ + sIn[nd * HH + k + 3] * w3_;
    }
#pragma unroll
    for (int nd = 0; nd < ND; nd++) sO4[nd * HH + tid] = acc[nd];
    __syncthreads();

    // out5 = out4 @ Wo + bo (256 -> 4), then log_softmax
    if (tid < ND * 4) {
        int nd = tid >> 2, c = tid & 3;
        float a = bo[c];
        for (int k = 0; k < HH; k += 4) {
            a += sO4[nd * HH + k + 0] * Wo[(k + 0) * 4 + c];
            a += sO4[nd * HH + k + 1] * Wo[(k + 1) * 4 + c];
            a += sO4[nd * HH + k + 2] * Wo[(k + 2) * 4 + c];
            a += sO4[nd * HH + k + 3] * Wo[(k + 3) * 4 + c];
        }
        s5[nd * 4 + c] = a;
    }
    __syncthreads();
    if (tid < ND) {
        float v0 = s5[tid * 4 + 0], v1 = s5[tid * 4 + 1];
        float v2 = s5[tid * 4 + 2], v3 = s5[tid * 4 + 3];
        float m = fmaxf(fmaxf(v0, v1), fmaxf(v2, v3));
        float lse = m + logf(expf(v0 - m) + expf(v1 - m) + expf(v2 - m) + expf(v3 - m));
        float* o = out + (size_t)(g0 + tid) * 4;
        o[0] = v0 - lse;
        o[1] = v1 - lse;
        o[2] = v2 - lse;
        o[3] = v3 - lse;
    }
}

// ---------------- launch ----------------
extern "C" void kernel_launch(void* const* d_in, const int* in_sizes, int n_in,
                              void* d_out, int out_size) {
    const float* x   = (const float*)d_in[0];
    const float* adj = (const float*)d_in[1];
    const float* We1 = (const float*)d_in[2];
    const float* be1 = (const float*)d_in[3];
    const float* We2 = (const float*)d_in[4];
    const float* be2 = (const float*)d_in[5];
    const float* Wn1 = (const float*)d_in[6];
    const float* bn1 = (const float*)d_in[7];
    const float* Wn2 = (const float*)d_in[8];
    const float* bn2 = (const float*)d_in[9];
    const float* Wo1 = (const float*)d_in[10];
    const float* bo1 = (const float*)d_in[11];
    const float* Wo  = (const float*)d_in[12];
    const float* bo  = (const float*)d_in[13];
    float* out = (float*)d_out;

    cudaFuncSetAttribute(k_main, cudaFuncAttributeMaxDynamicSharedMemorySize, SM_TOTAL);

    k_pre<<<NNODE, HH>>>(x, We1, be1);
    k_prew<<<HH, HH>>>(We2);
    dim3 g2(16, 8, 4);  // x = jb*2 + cb, y = ib, z = b
    k_main<<<g2, 256, SM_TOTAL>>>(adj, be2);
    k_post<<<NNODE / ND, 256>>>(x, Wn1, bn1, Wn2, bn2, Wo1, bo1, Wo, bo, out);
}